// round 7
// baseline (speedup 1.0000x reference)
#include <cuda_runtime.h>
#include <cstdint>

// ---------------------------------------------------------------------------
// FP8Linear: x [M=32768, K=1024] f32, w [N=1024, K=1024] f32, bias [1024] f32
// out[M,N] = (q(x) @ q(w)^T) * xs * ws + bias     (e4m3 per-tensor dynamic)
//
// R7: quantize to e4m3 then EXACTLY widen to fp16; GEMM via legacy
// mma.sync.m16n8k16.f16 (full-rate legacy path) instead of rate-limited
// fp8 QMMA (~28 cyc/SMSP measured). Numerics identical: e4m3 exact in f16,
// products exact, fp32 accumulate.
// ---------------------------------------------------------------------------
#define K_GLOBAL 1024
#define N_GLOBAL 1024
#define M_GLOBAL 32768
#define BM 128
#define BN 128
#define BK 64                        // k elements per chunk (128 bytes f16)
#define STAGES 3
#define ROWB 144                     // 128B data + 16B pad: conflict-free
#define A_STAGE (128 * ROWB)         // 18432
#define STAGE_BYTES (2 * 128 * ROWB) // 36864
#define SMEM_TOTAL (STAGES * STAGE_BYTES)  // 110592 (2 CTAs/SM: 221184)
#define KITERS (K_GLOBAL / BK)       // 16

__device__ unsigned char g_xh[(size_t)M_GLOBAL * K_GLOBAL * 2];  // f16 of e4m3(x)
__device__ unsigned char g_wh[(size_t)N_GLOBAL * K_GLOBAL * 2];  // f16 of e4m3(w)
__device__ unsigned int  g_amax_bits[2];   // [0]=x, [1]=w (float bits, >=0)

// ---------------------------------------------------------------------------
// helpers
// ---------------------------------------------------------------------------
__device__ __forceinline__ uint32_t smem_to_u32(const void* p) {
    uint32_t a;
    asm("{ .reg .u64 t; cvta.to.shared.u64 t, %1; cvt.u32.u64 %0, t; }" : "=r"(a) : "l"(p));
    return a;
}
__device__ __forceinline__ void cpasync16(uint32_t dst, const void* src) {
    asm volatile("cp.async.cg.shared.global [%0], [%1], 16;" :: "r"(dst), "l"(src));
}
__device__ __forceinline__ void cp_commit() {
    asm volatile("cp.async.commit_group;" ::: "memory");
}
template <int N>
__device__ __forceinline__ void cp_wait() {
    asm volatile("cp.async.wait_group %0;" :: "n"(N) : "memory");
}
__device__ __forceinline__ void ldsm4(uint32_t& r0, uint32_t& r1, uint32_t& r2,
                                      uint32_t& r3, uint32_t addr) {
    asm volatile("ldmatrix.sync.aligned.m8n8.x4.shared.b16 {%0,%1,%2,%3}, [%4];"
                 : "=r"(r0), "=r"(r1), "=r"(r2), "=r"(r3) : "r"(addr));
}
// fp16 MMA, fp32 accumulate. Non-volatile: pure register op.
__device__ __forceinline__ void mma_f16(float* c, const uint32_t* a, const uint32_t* b) {
    asm("mma.sync.aligned.m16n8k16.row.col.f32.f16.f16.f32 "
        "{%0,%1,%2,%3}, {%4,%5,%6,%7}, {%8,%9}, {%0,%1,%2,%3};"
        : "+f"(c[0]), "+f"(c[1]), "+f"(c[2]), "+f"(c[3])
        : "r"(a[0]), "r"(a[1]), "r"(a[2]), "r"(a[3]), "r"(b[0]), "r"(b[1]));
}
__device__ __forceinline__ float4 ldcs4(const float4* p) {
    float4 v;
    asm volatile("ld.global.cs.v4.f32 {%0,%1,%2,%3}, [%4];"
                 : "=f"(v.x), "=f"(v.y), "=f"(v.z), "=f"(v.w) : "l"(p));
    return v;
}

// ---------------------------------------------------------------------------
// Kernel 0: reset amax accumulators (graph replays must be deterministic)
// ---------------------------------------------------------------------------
__global__ void init_kernel() {
    g_amax_bits[0] = 0u;
    g_amax_bits[1] = 0u;
}

// ---------------------------------------------------------------------------
// Kernel 1: merged amax reduction for x (blocks < xBlocks) and w (rest)
// ---------------------------------------------------------------------------
__global__ void amax_kernel(const float4* __restrict__ xsrc, int xn4, int xBlocks,
                            const float4* __restrict__ wsrc, int wn4, int wBlocks) {
    int which = (blockIdx.x >= (unsigned)xBlocks);
    const float4* src = which ? wsrc : xsrc;
    int n4 = which ? wn4 : xn4;
    int bid = which ? ((int)blockIdx.x - xBlocks) : (int)blockIdx.x;
    int nb = which ? wBlocks : xBlocks;

    float m = 0.0f;
    for (int i = bid * blockDim.x + threadIdx.x; i < n4; i += nb * blockDim.x) {
        float4 v = ldcs4(src + i);
        m = fmaxf(m, fmaxf(fmaxf(fabsf(v.x), fabsf(v.y)),
                           fmaxf(fabsf(v.z), fabsf(v.w))));
    }
#pragma unroll
    for (int o = 16; o; o >>= 1) m = fmaxf(m, __shfl_xor_sync(0xFFFFFFFFu, m, o));
    if ((threadIdx.x & 31) == 0)
        atomicMax(&g_amax_bits[which], __float_as_uint(m));
}

// ---------------------------------------------------------------------------
// Kernel 2: quantize to e4m3 (RN satfinite == JAX cast), then exact e4m3->f16
// ---------------------------------------------------------------------------
__device__ __forceinline__ uint2 cvt4_e4m3_f16(float a, float b, float c, float d) {
    uint16_t lo, hi;
    // pack: lo byte = first arg of memory order
    asm("cvt.rn.satfinite.e4m3x2.f32 %0, %1, %2;" : "=h"(lo) : "f"(b), "f"(a));
    asm("cvt.rn.satfinite.e4m3x2.f32 %0, %1, %2;" : "=h"(hi) : "f"(d), "f"(c));
    uint2 r;
    asm("cvt.rn.f16x2.e4m3x2 %0, %1;" : "=r"(r.x) : "h"(lo));  // exact widen
    asm("cvt.rn.f16x2.e4m3x2 %0, %1;" : "=r"(r.y) : "h"(hi));
    return r;
}

__global__ void quant_kernel(const float4* __restrict__ xsrc, int xn16, int xBlocks,
                             const float4* __restrict__ wsrc, int wn16, int wBlocks) {
    int which = (blockIdx.x >= (unsigned)xBlocks);
    const float4* src = which ? wsrc : xsrc;
    int n16 = which ? wn16 : xn16;
    int bid = which ? ((int)blockIdx.x - xBlocks) : (int)blockIdx.x;
    int nb = which ? wBlocks : xBlocks;
    uint4* dst = (uint4*)(which ? g_wh : g_xh);

    float s = fmaxf(__uint_as_float(g_amax_bits[which]) / 448.0f, 1e-12f);
    for (int i = bid * blockDim.x + threadIdx.x; i < n16; i += nb * blockDim.x) {
        float4 a = ldcs4(src + 4 * i + 0);
        float4 b = ldcs4(src + 4 * i + 1);
        float4 c = ldcs4(src + 4 * i + 2);
        float4 d = ldcs4(src + 4 * i + 3);
        uint2 r0 = cvt4_e4m3_f16(a.x / s, a.y / s, a.z / s, a.w / s);
        uint2 r1 = cvt4_e4m3_f16(b.x / s, b.y / s, b.z / s, b.w / s);
        uint2 r2 = cvt4_e4m3_f16(c.x / s, c.y / s, c.z / s, c.w / s);
        uint2 r3 = cvt4_e4m3_f16(d.x / s, d.y / s, d.z / s, d.w / s);
        uint4 o0 = {r0.x, r0.y, r1.x, r1.y};
        uint4 o1 = {r2.x, r2.y, r3.x, r3.y};
        dst[2 * i + 0] = o0;
        dst[2 * i + 1] = o1;
    }
}

// ---------------------------------------------------------------------------
// Kernel 3: f16 GEMM. CTA 128x128, BK=64 (4 x k16 steps), 8 warps (4m x 2n),
// warp tile 32x64, 3-stage cp.async, 2 CTAs/SM.
// ---------------------------------------------------------------------------
extern __shared__ char smem[];

__global__ void __launch_bounds__(256, 2)
fp8_gemm_kernel(const float* __restrict__ bias, float* __restrict__ out) {
    const uint32_t sbase = smem_to_u32(smem);
    const int tid = threadIdx.x;
    const int wid = tid >> 5;
    const int lane = tid & 31;
    const int quad = lane >> 2;
    const int qi = lane & 3;
    const int warp_m = wid >> 1;     // 0..3
    const int warp_n = wid & 1;      // 0..1

    const int m0 = (int)(blockIdx.x >> 3) * BM;
    const int n0 = (int)(blockIdx.x & 7) * BN;

    // cp.async: thread loads one full 128B row slice per stage (8 x 16B).
    // tid<128 -> A rows, tid>=128 -> B rows. Row stride in gmem: 2048 B.
    const int mat = tid >> 7;
    const int row = tid & 127;
    const uint8_t* gRow = mat ? (g_wh + (size_t)(n0 + row) * 2048)
                              : (g_xh + (size_t)(m0 + row) * 2048);
    const uint32_t dRow = sbase + (uint32_t)mat * A_STAGE + (uint32_t)row * ROWB;

#pragma unroll
    for (int s = 0; s < STAGES - 1; s++) {
        uint32_t so = (uint32_t)s * STAGE_BYTES;
        const uint8_t* g = gRow + s * 128;
#pragma unroll
        for (int i = 0; i < 8; i++) cpasync16(dRow + so + i * 16, g + i * 16);
        cp_commit();
    }

    float acc[2][8][4];
#pragma unroll
    for (int mi = 0; mi < 2; mi++)
#pragma unroll
        for (int ni = 0; ni < 8; ni++)
#pragma unroll
            for (int j = 0; j < 4; j++) acc[mi][ni][j] = 0.0f;

    // ldmatrix bases (b16 tiles, 16B per 8 k-elements)
    // A m16k16 x4: rows warp_m*32+(lane&15), col sel (lane>>4)*16B
    const uint32_t aLdsmBase =
        sbase + (uint32_t)(warp_m * 32 + (lane & 15)) * ROWB + ((lane >> 4) << 4);
    // B: one x4 = two n8k16 frags (16 n-rows); rows warp_n*64+(lane&7)+((lane>=16)?8:0),
    // col sel (lane&8)*2
    const uint32_t bLdsmBase =
        sbase + A_STAGE +
        (uint32_t)(warp_n * 64 + (lane & 7) + ((lane >> 4) << 3)) * ROWB +
        ((lane & 8) << 1);

#pragma unroll 1
    for (int kc = 0; kc < KITERS; kc++) {
        cp_wait<STAGES - 2>();
        __syncthreads();

        if (kc + STAGES - 1 < KITERS) {
            uint32_t so = (uint32_t)((kc + STAGES - 1) % STAGES) * STAGE_BYTES;
            const uint8_t* g = gRow + (kc + STAGES - 1) * 128;
#pragma unroll
            for (int i = 0; i < 8; i++) cpasync16(dRow + so + i * 16, g + i * 16);
        }
        cp_commit();

        const uint32_t so = (uint32_t)(kc % STAGES) * STAGE_BYTES;
#pragma unroll
        for (int kk = 0; kk < 4; kk++) {     // four k16 steps per BK=64
            uint32_t a[2][4], b[8][2];
#pragma unroll
            for (int mi = 0; mi < 2; mi++)
                ldsm4(a[mi][0], a[mi][1], a[mi][2], a[mi][3],
                      aLdsmBase + so + mi * (16 * ROWB) + kk * 32);
#pragma unroll
            for (int nip = 0; nip < 4; nip++)
                ldsm4(b[2 * nip][0], b[2 * nip][1],
                      b[2 * nip + 1][0], b[2 * nip + 1][1],
                      bLdsmBase + so + nip * (16 * ROWB) + kk * 32);
#pragma unroll
            for (int mi = 0; mi < 2; mi++)
#pragma unroll
                for (int ni = 0; ni < 8; ni++)
                    mma_f16(acc[mi][ni], a[mi], b[ni]);
        }
    }
    cp_wait<0>();

    // ---------------- epilogue: scale + bias, float2 stores ----------------
    const float xs = fmaxf(__uint_as_float(g_amax_bits[0]) / 448.0f, 1e-12f);
    const float ws = fmaxf(__uint_as_float(g_amax_bits[1]) / 448.0f, 1e-12f);
    const float cs = xs * ws;

    const int colBase = n0 + warp_n * 64 + qi * 2;
    float2 bv[8];
#pragma unroll
    for (int ni = 0; ni < 8; ni++)
        bv[ni] = *(const float2*)(bias + colBase + ni * 8);

#pragma unroll
    for (int mi = 0; mi < 2; mi++) {
#pragma unroll
        for (int h = 0; h < 2; h++) {
            int orow_i = m0 + warp_m * 32 + mi * 16 + quad + h * 8;
            float* orow = out + (size_t)orow_i * N_GLOBAL + colBase;
#pragma unroll
            for (int ni = 0; ni < 8; ni++) {
                float2 v;
                v.x = fmaf(acc[mi][ni][2 * h + 0], cs, bv[ni].x);
                v.y = fmaf(acc[mi][ni][2 * h + 1], cs, bv[ni].y);
                *(float2*)(orow + ni * 8) = v;
            }
        }
    }
}

// ---------------------------------------------------------------------------
// Launch
// ---------------------------------------------------------------------------
extern "C" void kernel_launch(void* const* d_in, const int* in_sizes, int n_in,
                              void* d_out, int out_size) {
    const float* x = (const float*)d_in[0];      // [M, 1024]
    const float* w = (const float*)d_in[1];      // [1024, 1024]
    const float* bias = (const float*)d_in[2];   // [1024]
    float* out = (float*)d_out;

    int xM = in_sizes[0] / K_GLOBAL;             // 32768

    static bool attr_set = false;
    if (!attr_set) {
        cudaFuncSetAttribute(fp8_gemm_kernel,
                             cudaFuncAttributeMaxDynamicSharedMemorySize,
                             SMEM_TOTAL);
        attr_set = true;
    }

    const int xAB = 1184, wAB = 32;
    const int xQB = 1184, wQB = 128;

    init_kernel<<<1, 1>>>();
    amax_kernel<<<xAB + wAB, 256>>>((const float4*)x, in_sizes[0] / 4, xAB,
                                    (const float4*)w, in_sizes[1] / 4, wAB);
    quant_kernel<<<xQB + wQB, 256>>>((const float4*)x, in_sizes[0] / 16, xQB,
                                     (const float4*)w, in_sizes[1] / 16, wQB);

    int grid = (xM / BM) * (N_GLOBAL / BN);      // 2048
    fp8_gemm_kernel<<<grid, 256, SMEM_TOTAL>>>(bias, out);
}